// round 7
// baseline (speedup 1.0000x reference)
#include <cuda_runtime.h>
#include <math.h>

// Problem dims
#define BB   64      // batch
#define TT   512     // seq len
#define EE   256     // embed
#define HH   512     // hidden
#define GG   2048    // 4*HH
#define KC   64      // k rows per staged chunk
#define WSTR 36      // wt row stride in floats (144B, 16B-aligned)

// SMEM (floats): per half, double-buffered wt + ht; plus zb (final) + zbp (partial)
#define WTF  (KC * WSTR)   // 2304
#define HTF  (KC * BB)     // 4096
#define ZBF  (32 * BB)     // 2048
#define SMEM_FLOATS (2*2*WTF + 2*2*HTF + 2*ZBF)
#define SMEM_BYTES  (SMEM_FLOATS * 4)   // 118784

// ---------------- device scratch (allocation-free) ----------------
__device__ float g_X[TT * EE * BB];        // [t][e][b]
__device__ float g_h1[2][2][HH * BB];      // [dir][parity][k][b]
__device__ float g_h2[2][2][HH * BB];
__device__ unsigned g_bar[2];
__device__ int g_tok32;

// ---------------- helpers ----------------
__device__ __forceinline__ float fsig(float x) { return 1.0f / (1.0f + __expf(-x)); }
__device__ __forceinline__ float ftanh(float x) {
    return 2.0f / (1.0f + __expf(-2.0f * x)) - 1.0f;
}

__device__ __forceinline__ void ffma2(unsigned long long& d,
                                      unsigned long long a,
                                      unsigned long long b) {
    asm("fma.rn.f32x2 %0, %1, %2, %0;" : "+l"(d) : "l"(a), "l"(b));
}

__device__ __forceinline__ void grid_bar(unsigned* ctr, unsigned target) {
    __syncthreads();
    if (threadIdx.x == 0) {
        __threadfence();
        atomicAdd(ctr, 1u);
        while (*((volatile unsigned*)ctr) < target) { }
    }
    __syncthreads();
}

// ---------------- reset ----------------
__global__ void reset_kernel() {
    int i = blockIdx.x * blockDim.x + threadIdx.x;
    if (i < HH * BB) {
        #pragma unroll
        for (int d = 0; d < 2; d++)
            #pragma unroll
            for (int p = 0; p < 2; p++) { g_h1[d][p][i] = 0.0f; g_h2[d][p][i] = 0.0f; }
    }
    if (i == 0) { g_bar[0] = 0u; g_bar[1] = 0u; }
}

// ---------------- token dtype detect ----------------
__global__ void detect_kernel(const unsigned* tok) {
    __shared__ unsigned red[256];
    unsigned v = 0;
    for (int i = threadIdx.x; i < 16384; i += 256) v |= tok[2 * i + 1];
    red[threadIdx.x] = v;
    __syncthreads();
    for (int s = 128; s > 0; s >>= 1) {
        if (threadIdx.x < s) red[threadIdx.x] |= red[threadIdx.x + s];
        __syncthreads();
    }
    if (threadIdx.x == 0) g_tok32 = (red[0] != 0u) ? 1 : 0;
}

// ---------------- embedding gather (X[t][e][b]) ----------------
__global__ void gather_kernel(const void* tokens, const float* emb) {
    int t = blockIdx.x;
    int b = blockIdx.y;
    int e = threadIdx.x;
    long idx;
    if (g_tok32) idx = (long)((const int*)tokens)[b * TT + t];
    else         idx = (long)((const unsigned*)tokens)[(size_t)(b * TT + t) * 2];
    g_X[((size_t)t * EE + e) * BB + b] = emb[idx * EE + e];
}

// ---------------- staging (256 threads per half, R2 layout) ----------------
struct WStage { float4 a, b; };             // 8 cols of one gate, one k row
struct HStage { float4 v0, v1, v2, v3; };   // 16 consecutive floats of h chunk

__device__ __forceinline__ void load_w(WStage& s, const float* __restrict__ Wg,
                                       int k0, int skl, int sseg, int ub) {
    const float4* p = (const float4*)(Wg + (size_t)(k0 + skl) * GG + sseg * HH + ub);
    s.a = p[0];
    s.b = p[1];
}
__device__ __forceinline__ void store_w(const WStage& s, float* wt, int skl, int sseg) {
    float4* d = (float4*)(wt + skl * WSTR + sseg * 8);
    d[0] = s.a;
    d[1] = s.b;
}
__device__ __forceinline__ void load_h(HStage& s, const float* __restrict__ src,
                                       int k0, int htid) {
    const float4* p = (const float4*)(src + (size_t)k0 * BB);
    s.v0 = __ldcg(p + htid);
    s.v1 = __ldcg(p + htid + 256);
    s.v2 = __ldcg(p + htid + 512);
    s.v3 = __ldcg(p + htid + 768);
}
__device__ __forceinline__ void store_h(const HStage& s, float* ht, int htid) {
    float4* d = (float4*)ht;
    d[htid      ] = s.v0;
    d[htid + 256] = s.v1;
    d[htid + 512] = s.v2;
    d[htid + 768] = s.v3;
}

// ---------------- inner compute: one 64-k chunk, col-pair f32x2 ----------------
__device__ __forceinline__ void compute_chunk(unsigned long long acc2[4],
                                              const float* wt, const float* ht,
                                              int b, int cg) {
    #pragma unroll 16
    for (int k = 0; k < KC; k++) {
        unsigned hv = __float_as_uint(ht[k * BB + b]);
        unsigned long long hd;
        asm("mov.b64 %0, {%1, %1};" : "=l"(hd) : "r"(hv));
        const ulonglong2* w = (const ulonglong2*)(wt + k * WSTR + cg * 8);
        ulonglong2 w0 = w[0];            // cols (0,1),(2,3)
        ulonglong2 w1 = w[1];            // cols (4,5),(6,7)
        ffma2(acc2[0], w0.x, hd);
        ffma2(acc2[1], w0.y, hd);
        ffma2(acc2[2], w1.x, hd);
        ffma2(acc2[3], w1.y, hd);
    }
}

// ---------------- pipelined GEMM with k-split halves ----------------
// This half processes chunks c = half, half+2, ... (nk/KC is even for all calls)
__device__ __forceinline__ void gemm_pipe(unsigned long long acc2[4],
    const float* __restrict__ src, int nk, const float* __restrict__ Wg, int ub,
    int htid, int b, int cg, int half,
    float* wt0, float* wt1, float* ht0, float* ht1)
{
    const int skl  = htid & 63;     // k row staged by this thread
    const int sseg = htid >> 6;     // gate segment staged (8 cols)
    const int nit  = (nk / KC) >> 1;

    WStage ws; HStage hs;
    int c = half;
    load_w(ws, Wg, c * KC, skl, sseg, ub);
    load_h(hs, src, c * KC, htid);
    store_w(ws, wt0, skl, sseg);
    store_h(hs, ht0, htid);
    __syncthreads();
    for (int i = 0; i < nit; i++) {
        const float* wtc = (i & 1) ? wt1 : wt0;
        const float* htc = (i & 1) ? ht1 : ht0;
        float* wtn = (i & 1) ? wt0 : wt1;
        float* htn = (i & 1) ? ht0 : ht1;
        if (i + 1 < nit) {
            load_w(ws, Wg, (c + 2) * KC, skl, sseg, ub);
            load_h(hs, src, (c + 2) * KC, htid);
        }
        compute_chunk(acc2, wtc, htc, b, cg);
        if (i + 1 < nit) {
            store_w(ws, wtn, skl, sseg);
            store_h(hs, htn, htid);
        }
        __syncthreads();
        c += 2;
    }
}

// ---------------- persistent BiLSTM kernel (512 threads) ----------------
__global__ void __launch_bounds__(512, 1) lstm_kernel(
    const float* __restrict__ W1f, const float* __restrict__ U1f, const float* __restrict__ b1f,
    const float* __restrict__ W2f, const float* __restrict__ U2f, const float* __restrict__ b2f,
    const float* __restrict__ W1b, const float* __restrict__ U1b, const float* __restrict__ b1b,
    const float* __restrict__ W2b, const float* __restrict__ U2b, const float* __restrict__ b2b)
{
    const int dir  = blockIdx.x >> 6;
    const int cid  = blockIdx.x & 63;
    const int ub   = cid * 8;            // 8 hidden units -> 32 gate cols
    const int tid  = threadIdx.x;
    const int half = tid >> 8;           // k-split half 0/1
    const int htid = tid & 255;
    const int b    = htid & 63;          // batch lane
    const int cg   = htid >> 6;          // gate 0..3

    const float *W1, *U1, *b1, *W2, *U2, *b2;
    if (dir == 0) { W1 = W1f; U1 = U1f; b1 = b1f; W2 = W2f; U2 = U2f; b2 = b2f; }
    else          { W1 = W1b; U1 = U1b; b1 = b1b; W2 = W2b; U2 = U2b; b2 = b2b; }

    extern __shared__ float smem[];
    float* wtA0 = smem;                   // half 0 buffers
    float* wtA1 = wtA0 + WTF;
    float* wtB0 = wtA1 + WTF;             // half 1 buffers
    float* wtB1 = wtB0 + WTF;
    float* htA0 = wtB1 + WTF;
    float* htA1 = htA0 + HTF;
    float* htB0 = htA1 + HTF;
    float* htB1 = htB0 + HTF;
    float* zb   = htB1 + HTF;             // [32 local cols][64 b] final
    float* zbp  = zb + ZBF;               // partial (half 1)

    float* wt0 = half ? wtB0 : wtA0;
    float* wt1 = half ? wtB1 : wtA1;
    float* ht0 = half ? htB0 : htA0;
    float* ht1 = half ? htB1 : htA1;

    // bias (8 cols of gate cg)
    const float4 b1v0 = *(const float4*)(b1 + cg * HH + ub);
    const float4 b1v1 = *(const float4*)(b1 + cg * HH + ub + 4);
    const float4 b2v0 = *(const float4*)(b2 + cg * HH + ub);
    const float4 b2v1 = *(const float4*)(b2 + cg * HH + ub + 4);

    // pointwise: thread owns one (u, b) per layer
    const int pu = tid >> 6 & 7;   // same as (tid>>6) mod 8: 512 threads -> u 0..7 x b 0..63
    const int pb = tid & 63;
    const int zr = pu * BB + pb;   // gate g row offset = (g*8+pu)*BB+pb = zr + g*8*BB
    float c1 = 0.0f, c2 = 0.0f;
    unsigned target = 0;
    float* h1w[2] = { g_h1[dir][0], g_h1[dir][1] };
    float* h2w[2] = { g_h2[dir][0], g_h2[dir][1] };

    for (int t = 0; t < TT; t++) {
        const int ttx = dir ? (TT - 1 - t) : t;
        const int wp = t & 1, rp = wp ^ 1;

        // ================= Phase A: layer 1 =================
        unsigned long long acc2[4];
        #pragma unroll
        for (int j = 0; j < 4; j++) acc2[j] = 0ull;
        gemm_pipe(acc2, g_X + (size_t)ttx * EE * BB, EE, W1, ub, htid, b, cg, half,
                  wt0, wt1, ht0, ht1);
        gemm_pipe(acc2, h1w[rp], HH, U1, ub, htid, b, cg, half,
                  wt0, wt1, ht0, ht1);

        if (half == 1) {
            #pragma unroll
            for (int j = 0; j < 4; j++) {
                zbp[(cg * 8 + 2 * j    ) * BB + b] = __int_as_float((int)(acc2[j] & 0xffffffffull));
                zbp[(cg * 8 + 2 * j + 1) * BB + b] = __int_as_float((int)(acc2[j] >> 32));
            }
        }
        __syncthreads();
        if (half == 0) {
            const float* bp0 = (const float*)&b1v0;
            const float* bp1 = (const float*)&b1v1;
            #pragma unroll
            for (int j = 0; j < 4; j++) {
                float lo = __int_as_float((int)(acc2[j] & 0xffffffffull));
                float hi = __int_as_float((int)(acc2[j] >> 32));
                int je = 2 * j, jo = 2 * j + 1;
                float be = (je < 4) ? bp0[je] : bp1[je - 4];
                float bo = (jo < 4) ? bp0[jo] : bp1[jo - 4];
                zb[(cg * 8 + je) * BB + b] = lo + zbp[(cg * 8 + je) * BB + b] + be;
                zb[(cg * 8 + jo) * BB + b] = hi + zbp[(cg * 8 + jo) * BB + b] + bo;
            }
        }
        __syncthreads();
        {
            float iv = zb[zr];
            float fv = zb[zr +  8 * BB];
            float gv = zb[zr + 16 * BB];
            float ov = zb[zr + 24 * BB];
            c1 = fsig(fv) * c1 + fsig(iv) * ftanh(gv);
            __stcg(&h1w[wp][(ub + pu) * BB + pb], fsig(ov) * ftanh(c1));
        }
        target += 64;
        grid_bar(&g_bar[dir], target);

        // ================= Phase B: layer 2 =================
        #pragma unroll
        for (int j = 0; j < 4; j++) acc2[j] = 0ull;
        gemm_pipe(acc2, h1w[wp], HH, W2, ub, htid, b, cg, half,
                  wt0, wt1, ht0, ht1);
        gemm_pipe(acc2, h2w[rp], HH, U2, ub, htid, b, cg, half,
                  wt0, wt1, ht0, ht1);

        if (half == 1) {
            #pragma unroll
            for (int j = 0; j < 4; j++) {
                zbp[(cg * 8 + 2 * j    ) * BB + b] = __int_as_float((int)(acc2[j] & 0xffffffffull));
                zbp[(cg * 8 + 2 * j + 1) * BB + b] = __int_as_float((int)(acc2[j] >> 32));
            }
        }
        __syncthreads();
        if (half == 0) {
            const float* bp0 = (const float*)&b2v0;
            const float* bp1 = (const float*)&b2v1;
            #pragma unroll
            for (int j = 0; j < 4; j++) {
                float lo = __int_as_float((int)(acc2[j] & 0xffffffffull));
                float hi = __int_as_float((int)(acc2[j] >> 32));
                int je = 2 * j, jo = 2 * j + 1;
                float be = (je < 4) ? bp0[je] : bp1[je - 4];
                float bo = (jo < 4) ? bp0[jo] : bp1[jo - 4];
                zb[(cg * 8 + je) * BB + b] = lo + zbp[(cg * 8 + je) * BB + b] + be;
                zb[(cg * 8 + jo) * BB + b] = hi + zbp[(cg * 8 + jo) * BB + b] + bo;
            }
        }
        __syncthreads();
        {
            float iv = zb[zr];
            float fv = zb[zr +  8 * BB];
            float gv = zb[zr + 16 * BB];
            float ov = zb[zr + 24 * BB];
            c2 = fsig(fv) * c2 + fsig(iv) * ftanh(gv);
            __stcg(&h2w[wp][(ub + pu) * BB + pb], fsig(ov) * ftanh(c2));
        }
        target += 64;
        grid_bar(&g_bar[dir], target);
    }
}

// ---------------- final dense head ----------------
__global__ void dense_kernel(const float* __restrict__ Wd, const float* __restrict__ bd,
                             float* __restrict__ out) {
    int tid = threadIdx.x;
    if (tid >= 320) return;
    int bb2 = tid / 5, o = tid % 5;
    float s = bd[o];
    for (int j = 0; j < HH; j++) s += g_h2[0][1][j * BB + bb2] * Wd[j * 5 + o];
    for (int j = 0; j < HH; j++) s += g_h2[1][1][j * BB + bb2] * Wd[(HH + j) * 5 + o];
    out[bb2 * 5 + o] = s;
}

// ---------------- launch ----------------
extern "C" void kernel_launch(void* const* d_in, const int* in_sizes, int n_in,
                              void* d_out, int out_size) {
    const void*  tokens = d_in[0];
    const float* emb = (const float*)d_in[1];
    const float* W1f = (const float*)d_in[2];
    const float* U1f = (const float*)d_in[3];
    const float* b1f = (const float*)d_in[4];
    const float* W2f = (const float*)d_in[5];
    const float* U2f = (const float*)d_in[6];
    const float* b2f = (const float*)d_in[7];
    const float* W1b = (const float*)d_in[8];
    const float* U1b = (const float*)d_in[9];
    const float* b1b = (const float*)d_in[10];
    const float* W2b = (const float*)d_in[11];
    const float* U2b = (const float*)d_in[12];
    const float* b2b = (const float*)d_in[13];
    const float* Wd  = (const float*)d_in[14];
    const float* bd  = (const float*)d_in[15];
    float* out = (float*)d_out;

    cudaFuncSetAttribute(lstm_kernel, cudaFuncAttributeMaxDynamicSharedMemorySize, SMEM_BYTES);

    reset_kernel<<<128, 256>>>();
    detect_kernel<<<1, 256>>>((const unsigned*)tokens);
    dim3 gg(TT, BB);
    gather_kernel<<<gg, 256>>>(tokens, emb);
    lstm_kernel<<<128, 512, SMEM_BYTES>>>(W1f, U1f, b1f, W2f, U2f, b2f,
                                          W1b, U1b, b1b, W2b, U2b, b2b);
    dense_kernel<<<1, 320>>>(Wd, bd, out);
}

// round 8
// speedup vs baseline: 1.5377x; 1.5377x over previous
#include <cuda_runtime.h>
#include <math.h>

// Problem dims
#define BB   64      // batch
#define TT   512     // seq len
#define EE   256     // embed
#define HH   512     // hidden
#define GG   2048    // 4*HH
#define KC   64      // k-chunk
#define WSTR 36      // weight tile row stride (32 cols + pad, 16B-aligned rows)

// ---------------- device scratch (allocation-free) ----------------
__device__ float g_X[TT * EE * BB];        // [t][e][b]  33.5 MB
__device__ float g_h1[2][2][HH * BB];      // [dir][parity][k][b]
__device__ float g_h2[2][2][HH * BB];
__device__ unsigned g_bar[2];
__device__ int g_tok32;                    // 1 if tokens are int32

// ---------------- helpers ----------------
__device__ __forceinline__ float fsig(float x) { return 1.0f / (1.0f + __expf(-x)); }
__device__ __forceinline__ float ftanh(float x) {
    return 2.0f / (1.0f + __expf(-2.0f * x)) - 1.0f;
}

__device__ __forceinline__ void ffma2(unsigned long long& d,
                                      unsigned long long a,
                                      unsigned long long b) {
    asm("fma.rn.f32x2 %0, %1, %2, %0;" : "+l"(d) : "l"(a), "l"(b));
}

__device__ __forceinline__ void grid_bar(unsigned* ctr, unsigned target) {
    __syncthreads();
    if (threadIdx.x == 0) {
        __threadfence();                 // release our h writes to GPU scope
        atomicAdd(ctr, 1u);
        while (*((volatile unsigned*)ctr) < target) { }
    }
    __syncthreads();
}

// ---------------- reset ----------------
__global__ void reset_kernel() {
    int i = blockIdx.x * blockDim.x + threadIdx.x;
    if (i < HH * BB) {
        #pragma unroll
        for (int d = 0; d < 2; d++)
            #pragma unroll
            for (int p = 0; p < 2; p++) { g_h1[d][p][i] = 0.0f; g_h2[d][p][i] = 0.0f; }
    }
    if (i == 0) { g_bar[0] = 0u; g_bar[1] = 0u; }
}

// ---------------- token dtype detect ----------------
// If tokens are int64 little-endian with values < 50000, every odd 32-bit word is 0.
__global__ void detect_kernel(const unsigned* tok) {
    __shared__ unsigned red[256];
    unsigned v = 0;
    for (int i = threadIdx.x; i < 16384; i += 256) v |= tok[2 * i + 1];
    red[threadIdx.x] = v;
    __syncthreads();
    for (int s = 128; s > 0; s >>= 1) {
        if (threadIdx.x < s) red[threadIdx.x] |= red[threadIdx.x + s];
        __syncthreads();
    }
    if (threadIdx.x == 0) g_tok32 = (red[0] != 0u) ? 1 : 0;
}

// ---------------- embedding gather (X[t][e][b]) ----------------
__global__ void gather_kernel(const void* tokens, const float* emb) {
    int t = blockIdx.x;        // 0..511
    int b = blockIdx.y;        // 0..63
    int e = threadIdx.x;       // 0..255
    long idx;
    if (g_tok32) idx = (long)((const int*)tokens)[b * TT + t];
    else         idx = (long)((const unsigned*)tokens)[(size_t)(b * TT + t) * 2];
    g_X[((size_t)t * EE + e) * BB + b] = emb[idx * EE + e];
}

// ---------------- GEMM chunk helper (R2 structure, FFMA2 inner loop) ----------
// acc2[j] pairs cols (2j, 2j+1) of this thread's 8 gate columns.
__device__ __forceinline__ void gemm_chunks(
    unsigned long long acc2[4], const float* __restrict__ src, int nk,
    const float* __restrict__ Wg, int ub,
    int tid, int b, int cg, float* wt, float* ht)
{
    const int skl = tid & 63;       // k-local row this thread stages
    const int sseg = tid >> 6;      // gate segment this thread stages
    for (int k0 = 0; k0 < nk; k0 += KC) {
        // prefetch into registers (overlaps previous chunk's compute)
        const float4* wsrc = (const float4*)(Wg + (size_t)(k0 + skl) * GG + sseg * HH + ub);
        float4 wv0 = wsrc[0];
        float4 wv1 = wsrc[1];
        const float4* hsrc = (const float4*)(src + (size_t)k0 * BB);
        float4 h0 = __ldcg(hsrc + tid);
        float4 h1 = __ldcg(hsrc + tid + 256);
        float4 h2 = __ldcg(hsrc + tid + 512);
        float4 h3 = __ldcg(hsrc + tid + 768);
        __syncthreads();   // previous chunk's compute done before overwrite
        ((float4*)(wt + skl * WSTR + sseg * 8))[0] = wv0;
        ((float4*)(wt + skl * WSTR + sseg * 8))[1] = wv1;
        ((float4*)ht)[tid      ] = h0;
        ((float4*)ht)[tid + 256] = h1;
        ((float4*)ht)[tid + 512] = h2;
        ((float4*)ht)[tid + 768] = h3;
        __syncthreads();
        #pragma unroll 16
        for (int k = 0; k < KC; k++) {
            unsigned hv = __float_as_uint(ht[k * BB + b]);
            unsigned long long hd;
            asm("mov.b64 %0, {%1, %1};" : "=l"(hd) : "r"(hv));
            const ulonglong2* wrow = (const ulonglong2*)(wt + k * WSTR + cg * 8);
            ulonglong2 w0 = wrow[0];   // col pairs (0,1),(2,3)
            ulonglong2 w1 = wrow[1];   // col pairs (4,5),(6,7)
            ffma2(acc2[0], w0.x, hd);
            ffma2(acc2[1], w0.y, hd);
            ffma2(acc2[2], w1.x, hd);
            ffma2(acc2[3], w1.y, hd);
        }
    }
}

// ---------------- persistent BiLSTM kernel ----------------
__global__ void __launch_bounds__(256, 1) lstm_kernel(
    const float* __restrict__ W1f, const float* __restrict__ U1f, const float* __restrict__ b1f,
    const float* __restrict__ W2f, const float* __restrict__ U2f, const float* __restrict__ b2f,
    const float* __restrict__ W1b, const float* __restrict__ U1b, const float* __restrict__ b1b,
    const float* __restrict__ W2b, const float* __restrict__ U2b, const float* __restrict__ b2b)
{
    const int dir = blockIdx.x >> 6;     // 0 = fwd, 1 = bwd
    const int cid = blockIdx.x & 63;     // CTA within direction
    const int ub  = cid * 8;             // base hidden unit
    const int tid = threadIdx.x;
    const int b   = tid & 63;
    const int cg  = tid >> 6;            // gate: 0=i 1=f 2=g 3=o

    const float *W1, *U1, *b1, *W2, *U2, *b2;
    if (dir == 0) { W1 = W1f; U1 = U1f; b1 = b1f; W2 = W2f; U2 = U2f; b2 = b2f; }
    else          { W1 = W1b; U1 = U1b; b1 = b1b; W2 = W2b; U2 = U2b; b2 = b2b; }

    __shared__ float wt[KC * WSTR];      // 9216 B
    __shared__ float ht[KC * BB];        // 16384 B
    __shared__ float zb[GG];             // 8192 B (32 cols x 64 b as [gate*8+u][b])

    // cell state lives in registers: this thread owns pairs p=tid and p=tid+256,
    // where p = u*64 + b' (u in 0..7 local unit, b' batch)
    float c1_0 = 0.0f, c1_1 = 0.0f, c2_0 = 0.0f, c2_1 = 0.0f;
    unsigned target = 0;
    float* h1w[2] = { g_h1[dir][0], g_h1[dir][1] };
    float* h2w[2] = { g_h2[dir][0], g_h2[dir][1] };

    for (int t = 0; t < TT; t++) {
        const int ttx = dir ? (TT - 1 - t) : t;
        const int wp = t & 1, rp = wp ^ 1;

        // ================= Phase A: layer-1 gates =================
        unsigned long long acc2[4];
        #pragma unroll
        for (int j = 0; j < 4; j++) acc2[j] = 0ull;
        gemm_chunks(acc2, g_X + (size_t)ttx * EE * BB, EE, W1, ub, tid, b, cg, wt, ht);
        gemm_chunks(acc2, h1w[rp], HH, U1, ub, tid, b, cg, wt, ht);

        __syncthreads();
        #pragma unroll
        for (int j = 0; j < 4; j++) {
            float lo = __int_as_float((int)(acc2[j] & 0xffffffffull));
            float hi = __int_as_float((int)(acc2[j] >> 32));
            zb[(cg * 8 + 2 * j    ) * BB + b] = lo + b1[cg * HH + ub + 2 * j];
            zb[(cg * 8 + 2 * j + 1) * BB + b] = hi + b1[cg * HH + ub + 2 * j + 1];
        }
        __syncthreads();
        {
            // pair 0
            int u = tid >> 6, bb2 = tid & 63;
            float iv = zb[( 0 + u) * BB + bb2];
            float fv = zb[( 8 + u) * BB + bb2];
            float gv = zb[(16 + u) * BB + bb2];
            float ov = zb[(24 + u) * BB + bb2];
            float c = fsig(fv) * c1_0 + fsig(iv) * ftanh(gv);
            c1_0 = c;
            __stcg(&h1w[wp][(ub + u) * BB + bb2], fsig(ov) * ftanh(c));
            // pair 1
            u += 4;
            iv = zb[( 0 + u) * BB + bb2];
            fv = zb[( 8 + u) * BB + bb2];
            gv = zb[(16 + u) * BB + bb2];
            ov = zb[(24 + u) * BB + bb2];
            c = fsig(fv) * c1_1 + fsig(iv) * ftanh(gv);
            c1_1 = c;
            __stcg(&h1w[wp][(ub + u) * BB + bb2], fsig(ov) * ftanh(c));
        }
        target += 64;
        grid_bar(&g_bar[dir], target);

        // ================= Phase B: layer-2 gates =================
        #pragma unroll
        for (int j = 0; j < 4; j++) acc2[j] = 0ull;
        gemm_chunks(acc2, h1w[wp], HH, W2, ub, tid, b, cg, wt, ht);
        gemm_chunks(acc2, h2w[rp], HH, U2, ub, tid, b, cg, wt, ht);

        __syncthreads();
        #pragma unroll
        for (int j = 0; j < 4; j++) {
            float lo = __int_as_float((int)(acc2[j] & 0xffffffffull));
            float hi = __int_as_float((int)(acc2[j] >> 32));
            zb[(cg * 8 + 2 * j    ) * BB + b] = lo + b2[cg * HH + ub + 2 * j];
            zb[(cg * 8 + 2 * j + 1) * BB + b] = hi + b2[cg * HH + ub + 2 * j + 1];
        }
        __syncthreads();
        {
            int u = tid >> 6, bb2 = tid & 63;
            float iv = zb[( 0 + u) * BB + bb2];
            float fv = zb[( 8 + u) * BB + bb2];
            float gv = zb[(16 + u) * BB + bb2];
            float ov = zb[(24 + u) * BB + bb2];
            float c = fsig(fv) * c2_0 + fsig(iv) * ftanh(gv);
            c2_0 = c;
            __stcg(&h2w[wp][(ub + u) * BB + bb2], fsig(ov) * ftanh(c));
            u += 4;
            iv = zb[( 0 + u) * BB + bb2];
            fv = zb[( 8 + u) * BB + bb2];
            gv = zb[(16 + u) * BB + bb2];
            ov = zb[(24 + u) * BB + bb2];
            c = fsig(fv) * c2_1 + fsig(iv) * ftanh(gv);
            c2_1 = c;
            __stcg(&h2w[wp][(ub + u) * BB + bb2], fsig(ov) * ftanh(c));
        }
        target += 64;
        grid_bar(&g_bar[dir], target);
    }
}

// ---------------- final dense head ----------------
__global__ void dense_kernel(const float* __restrict__ Wd, const float* __restrict__ bd,
                             float* __restrict__ out) {
    int tid = threadIdx.x;
    if (tid >= 320) return;
    int bb2 = tid / 5, o = tid % 5;
    // last step t=511 wrote parity 1
    float s = bd[o];
    for (int j = 0; j < HH; j++) s += g_h2[0][1][j * BB + bb2] * Wd[j * 5 + o];
    for (int j = 0; j < HH; j++) s += g_h2[1][1][j * BB + bb2] * Wd[(HH + j) * 5 + o];
    out[bb2 * 5 + o] = s;
}

// ---------------- launch ----------------
extern "C" void kernel_launch(void* const* d_in, const int* in_sizes, int n_in,
                              void* d_out, int out_size) {
    const void*  tokens = d_in[0];
    const float* emb = (const float*)d_in[1];
    const float* W1f = (const float*)d_in[2];
    const float* U1f = (const float*)d_in[3];
    const float* b1f = (const float*)d_in[4];
    const float* W2f = (const float*)d_in[5];
    const float* U2f = (const float*)d_in[6];
    const float* b2f = (const float*)d_in[7];
    const float* W1b = (const float*)d_in[8];
    const float* U1b = (const float*)d_in[9];
    const float* b1b = (const float*)d_in[10];
    const float* W2b = (const float*)d_in[11];
    const float* U2b = (const float*)d_in[12];
    const float* b2b = (const float*)d_in[13];
    const float* Wd  = (const float*)d_in[14];
    const float* bd  = (const float*)d_in[15];
    float* out = (float*)d_out;

    reset_kernel<<<128, 256>>>();
    detect_kernel<<<1, 256>>>((const unsigned*)tokens);
    dim3 gg(TT, BB);
    gather_kernel<<<gg, 256>>>(tokens, emb);
    lstm_kernel<<<128, 256>>>(W1f, U1f, b1f, W2f, U2f, b2f,
                              W1b, U1b, b1b, W2b, U2b, b2b);
    dense_kernel<<<1, 320>>>(Wd, bd, out);
}